// round 6
// baseline (speedup 1.0000x reference)
#include <cuda_runtime.h>
#include <stdint.h>

#define NT 8192
#define TK 2
#define NE 8
#define DM 1024
#define DF 2048
#define CAP 3072

// ---- persistent scratch (device globals; no runtime allocation allowed) ----
__device__ int   g_cnt[NE];
__device__ int   g_tok[NE * CAP];          // zero-init -> always a valid token id
__device__ float g_wt[NE * CAP];
__device__ float g_hidden[(size_t)NE * CAP * DF];   // 201 MB

// ---------------- dispatch ----------------
__global__ void k_zero() { if (threadIdx.x < NE) g_cnt[threadIdx.x] = 0; }

__global__ void k_dispatch(const int* __restrict__ idx, const float* __restrict__ w) {
    int i = blockIdx.x * blockDim.x + threadIdx.x;
    if (i >= NT * TK) return;
    int e = idx[i];
    int p = atomicAdd(&g_cnt[e], 1);
    if (p < CAP) {
        g_tok[e * CAP + p] = i >> 1;
        g_wt[e * CAP + p]  = w[i];
    }
}

// ---------------- packed f32x2 helpers ----------------
__device__ __forceinline__ uint64_t pack2(float v) {
    uint64_t r; asm("mov.b64 %0, {%1, %1};" : "=l"(r) : "f"(v)); return r;
}
__device__ __forceinline__ uint64_t fma2(uint64_t a, uint64_t b, uint64_t c) {
    uint64_t d; asm("fma.rn.f32x2 %0, %1, %2, %3;" : "=l"(d) : "l"(a), "l"(b), "l"(c)); return d;
}
__device__ __forceinline__ float2 up2(uint64_t v) {
    float2 f; asm("mov.b64 {%0, %1}, %2;" : "=f"(f.x), "=f"(f.y) : "l"(v)); return f;
}
__device__ __forceinline__ void red2(float* p, float a, float b) {
    asm volatile("red.global.add.v2.f32 [%0], {%1, %2};" :: "l"(p), "f"(a), "f"(b) : "memory");
}

// ---------------- GEMM1: fused gate/value + SwiGLU ----------------
// tile 128m x (64n per matrix), BK=16, 256 threads, micro 8m x 4n x 2mat
__global__ __launch_bounds__(256, 2) void k_gemm1(const float* __restrict__ x,
                                                  const float* __restrict__ w1,
                                                  const float* __restrict__ w2) {
    const int e   = blockIdx.z;
    const int cnt = g_cnt[e];
    const int m0  = blockIdx.y * 128;
    if (m0 >= cnt) return;
    const int n0  = blockIdx.x * 64;

    __shared__ float As[2][16][132];
    __shared__ float B1s[2][16][64];
    __shared__ float B2s[2][16][64];
    __shared__ int   toks[128];

    const int tid = threadIdx.x;
    if (tid < 128) toks[tid] = g_tok[e * CAP + m0 + tid];
    __syncthreads();

    const int ar  = tid >> 2;            // 0..63
    const int akq = (tid & 3) * 4;       // k offset (floats)
    const float* ap0 = x + (size_t)toks[ar]      * DM + akq;
    const float* ap1 = x + (size_t)toks[ar + 64] * DM + akq;

    const int bkr = tid >> 4;            // 0..15
    const int bnc = (tid & 15) * 4;
    const float* b1p = w1 + (size_t)e * DM * DF + (size_t)bkr * DF + n0 + bnc;
    const float* b2p = w2 + (size_t)e * DM * DF + (size_t)bkr * DF + n0 + bnc;

    const int tx = tid & 15, ty = tid >> 4;

    uint64_t acc1[8][2], acc2[8][2];
#pragma unroll
    for (int i = 0; i < 8; i++) { acc1[i][0] = acc1[i][1] = 0ull; acc2[i][0] = acc2[i][1] = 0ull; }

    float4 ra0 = *(const float4*)(ap0);
    float4 ra1 = *(const float4*)(ap1);
    float4 rb1 = *(const float4*)(b1p);
    float4 rb2 = *(const float4*)(b2p);

    int buf = 0;
    for (int t = 0; t < DM / 16; t++) {
        As[buf][akq + 0][ar] = ra0.x; As[buf][akq + 1][ar] = ra0.y;
        As[buf][akq + 2][ar] = ra0.z; As[buf][akq + 3][ar] = ra0.w;
        As[buf][akq + 0][ar + 64] = ra1.x; As[buf][akq + 1][ar + 64] = ra1.y;
        As[buf][akq + 2][ar + 64] = ra1.z; As[buf][akq + 3][ar + 64] = ra1.w;
        *(float4*)&B1s[buf][bkr][bnc] = rb1;
        *(float4*)&B2s[buf][bkr][bnc] = rb2;
        __syncthreads();

        if (t + 1 < DM / 16) {
            int k0 = (t + 1) * 16;
            ra0 = *(const float4*)(ap0 + k0);
            ra1 = *(const float4*)(ap1 + k0);
            rb1 = *(const float4*)(b1p + (size_t)k0 * DF);
            rb2 = *(const float4*)(b2p + (size_t)k0 * DF);
        }

#pragma unroll
        for (int kk = 0; kk < 16; kk++) {
            float4 a0 = *(const float4*)&As[buf][kk][ty * 8];
            float4 a1 = *(const float4*)&As[buf][kk][ty * 8 + 4];
            uint64_t aa[8] = {pack2(a0.x), pack2(a0.y), pack2(a0.z), pack2(a0.w),
                              pack2(a1.x), pack2(a1.y), pack2(a1.z), pack2(a1.w)};
            const uint64_t* b1 = (const uint64_t*)&B1s[buf][kk][tx * 4];
            const uint64_t* b2 = (const uint64_t*)&B2s[buf][kk][tx * 4];
            uint64_t b10 = b1[0], b11 = b1[1], b20 = b2[0], b21 = b2[1];
#pragma unroll
            for (int i = 0; i < 8; i++) {
                acc1[i][0] = fma2(aa[i], b10, acc1[i][0]);
                acc1[i][1] = fma2(aa[i], b11, acc1[i][1]);
                acc2[i][0] = fma2(aa[i], b20, acc2[i][0]);
                acc2[i][1] = fma2(aa[i], b21, acc2[i][1]);
            }
        }
        buf ^= 1;
    }

    // epilogue: hidden = silu(gate) * value
#pragma unroll
    for (int i = 0; i < 8; i++) {
        float* hrow = g_hidden + (size_t)(e * CAP + m0 + ty * 8 + i) * DF + n0 + tx * 4;
        float2 g0 = up2(acc1[i][0]), g1 = up2(acc1[i][1]);
        float2 v0 = up2(acc2[i][0]), v1 = up2(acc2[i][1]);
        float4 h;
        h.x = g0.x / (1.0f + __expf(-g0.x)) * v0.x;
        h.y = g0.y / (1.0f + __expf(-g0.y)) * v0.y;
        h.z = g1.x / (1.0f + __expf(-g1.x)) * v1.x;
        h.w = g1.y / (1.0f + __expf(-g1.y)) * v1.y;
        *(float4*)hrow = h;
    }
}

// ---------------- GEMM2: hidden @ w3, weighted scatter-add ----------------
// tile 128m x 128n, BK=16, 256 threads, micro 8m x 8n (n split as tx*4 and 64+tx*4)
__global__ __launch_bounds__(256, 2) void k_gemm2(const float* __restrict__ w3,
                                                  float* __restrict__ out) {
    const int e   = blockIdx.z;
    const int cnt = g_cnt[e];
    const int m0  = blockIdx.y * 128;
    if (m0 >= cnt) return;
    const int n0  = blockIdx.x * 128;

    __shared__ float As[2][16][132];
    __shared__ float Bs[2][16][128];
    __shared__ int   toks[128];
    __shared__ float wts[128];

    const int tid = threadIdx.x;
    if (tid < 128) { toks[tid] = g_tok[e * CAP + m0 + tid]; wts[tid] = g_wt[e * CAP + m0 + tid]; }

    const int ar  = tid >> 2;            // 0..63
    const int akq = (tid & 3) * 4;
    const float* ap0 = g_hidden + (size_t)(e * CAP + m0 + ar) * DF + akq;
    const float* ap1 = ap0 + (size_t)64 * DF;

    const int bkr = tid >> 5;            // 0..7 (rows bkr, bkr+8)
    const int bnc = (tid & 31) * 4;
    const float* bp = w3 + (size_t)e * DF * DM + (size_t)bkr * DM + n0 + bnc;

    const int tx = tid & 15, ty = tid >> 4;

    uint64_t acc[8][4];
#pragma unroll
    for (int i = 0; i < 8; i++) { acc[i][0] = acc[i][1] = acc[i][2] = acc[i][3] = 0ull; }

    float4 ra0 = *(const float4*)(ap0);
    float4 ra1 = *(const float4*)(ap1);
    float4 rb0 = *(const float4*)(bp);
    float4 rb1 = *(const float4*)(bp + (size_t)8 * DM);

    int buf = 0;
    for (int t = 0; t < DF / 16; t++) {
        As[buf][akq + 0][ar] = ra0.x; As[buf][akq + 1][ar] = ra0.y;
        As[buf][akq + 2][ar] = ra0.z; As[buf][akq + 3][ar] = ra0.w;
        As[buf][akq + 0][ar + 64] = ra1.x; As[buf][akq + 1][ar + 64] = ra1.y;
        As[buf][akq + 2][ar + 64] = ra1.z; As[buf][akq + 3][ar + 64] = ra1.w;
        *(float4*)&Bs[buf][bkr][bnc]     = rb0;
        *(float4*)&Bs[buf][bkr + 8][bnc] = rb1;
        __syncthreads();

        if (t + 1 < DF / 16) {
            int k0 = (t + 1) * 16;
            ra0 = *(const float4*)(ap0 + k0);
            ra1 = *(const float4*)(ap1 + k0);
            rb0 = *(const float4*)(bp + (size_t)k0 * DM);
            rb1 = *(const float4*)(bp + (size_t)(k0 + 8) * DM);
        }

#pragma unroll
        for (int kk = 0; kk < 16; kk++) {
            float4 a0 = *(const float4*)&As[buf][kk][ty * 8];
            float4 a1 = *(const float4*)&As[buf][kk][ty * 8 + 4];
            uint64_t aa[8] = {pack2(a0.x), pack2(a0.y), pack2(a0.z), pack2(a0.w),
                              pack2(a1.x), pack2(a1.y), pack2(a1.z), pack2(a1.w)};
            const uint64_t* bL = (const uint64_t*)&Bs[buf][kk][tx * 4];
            const uint64_t* bH = (const uint64_t*)&Bs[buf][kk][64 + tx * 4];
            uint64_t b0 = bL[0], b1 = bL[1], b2 = bH[0], b3 = bH[1];
#pragma unroll
            for (int i = 0; i < 8; i++) {
                acc[i][0] = fma2(aa[i], b0, acc[i][0]);
                acc[i][1] = fma2(aa[i], b1, acc[i][1]);
                acc[i][2] = fma2(aa[i], b2, acc[i][2]);
                acc[i][3] = fma2(aa[i], b3, acc[i][3]);
            }
        }
        buf ^= 1;
    }

    // epilogue: out[token] += weight * val   (exactly TOP_K=2 adds/element)
#pragma unroll
    for (int i = 0; i < 8; i++) {
        int r = ty * 8 + i;
        if (m0 + r < cnt) {
            float wgt  = wts[r];
            float* o   = out + (size_t)toks[r] * DM + n0;
            float2 p;
            p = up2(acc[i][0]); red2(o + tx * 4,          wgt * p.x, wgt * p.y);
            p = up2(acc[i][1]); red2(o + tx * 4 + 2,      wgt * p.x, wgt * p.y);
            p = up2(acc[i][2]); red2(o + 64 + tx * 4,     wgt * p.x, wgt * p.y);
            p = up2(acc[i][3]); red2(o + 64 + tx * 4 + 2, wgt * p.x, wgt * p.y);
        }
    }
}

// ---------------- launch ----------------
extern "C" void kernel_launch(void* const* d_in, const int* in_sizes, int n_in,
                              void* d_out, int out_size) {
    const float* x   = (const float*)d_in[0];
    const int*   idx = (const int*)  d_in[1];
    const float* ew  = (const float*)d_in[2];
    const float* w1  = (const float*)d_in[3];
    const float* w2  = (const float*)d_in[4];
    const float* w3  = (const float*)d_in[5];
    float* out = (float*)d_out;

    cudaMemsetAsync(out, 0, (size_t)out_size * sizeof(float));
    k_zero<<<1, 32>>>();
    k_dispatch<<<(NT * TK + 255) / 256, 256>>>(idx, ew);

    dim3 g1(DF / 64, CAP / 128, NE);
    k_gemm1<<<g1, 256>>>(x, w1, w2);

    dim3 g2(DM / 128, CAP / 128, NE);
    k_gemm2<<<g2, 256>>>(w3, out);
}

// round 9
// speedup vs baseline: 3.8679x; 3.8679x over previous
#include <cuda_runtime.h>
#include <cuda_bf16.h>
#include <stdint.h>

#define NT 8192
#define TK 2
#define NE 8
#define DM 1024
#define DF 2048
#define CAP 3072
#define TS 16384
#define IDESC 0x8200490u  // kind::f16: F32 acc, bf16 A/B, M=128, N=128

// ---- arch-feature gate: tcgen05 only exists in sm_103a/'f' compile passes ----
#if defined(__CUDA_ARCH__) && (__CUDA_ARCH__ >= 1000) && \
    (defined(__CUDA_ARCH_FEAT_SM103_ALL) || defined(__CUDA_ARCH_FEAT_SM100_ALL) || \
     defined(__CUDA_ARCH_FEAT_SM101_ALL) || defined(__CUDA_ARCH_SPECIFIC__) || \
     defined(__CUDA_ARCH_FAMILY_SPECIFIC__))
#define TC 1
#else
#define TC 0
#endif

// ---- persistent scratch ----
__device__ int   g_use_tc;
__device__ int   g_cnt[NE];
__device__ int   g_tok[NE * CAP];
__device__ float g_wt[NE * CAP];
__device__ float g_hidden[(size_t)NE * CAP * DF];                 // SIMT path
__device__ __align__(128) __nv_bfloat16 g_ah[(size_t)NE*CAP*DM], g_al[(size_t)NE*CAP*DM];
__device__ __align__(128) __nv_bfloat16 g_w1h[(size_t)NE*DF*DM], g_w1l[(size_t)NE*DF*DM];
__device__ __align__(128) __nv_bfloat16 g_w2h[(size_t)NE*DF*DM], g_w2l[(size_t)NE*DF*DM];
__device__ __align__(128) __nv_bfloat16 g_w3h[(size_t)NE*DM*DF], g_w3l[(size_t)NE*DM*DF];
__device__ __align__(128) __nv_bfloat16 g_hh[(size_t)NE*CAP*DF], g_hl[(size_t)NE*CAP*DF];

// ---- helpers ----
__device__ __forceinline__ uint32_t smem_u32(const void* p) {
    uint32_t a;
    asm("{ .reg .u64 t; cvta.to.shared.u64 t, %1; cvt.u32.u64 %0, t; }" : "=r"(a) : "l"(p));
    return a;
}
__device__ __forceinline__ uint32_t pk(float hi, float lo) {
    uint32_t r; asm("cvt.rn.bf16x2.f32 %0, %1, %2;" : "=r"(r) : "f"(hi), "f"(lo)); return r;
}
__device__ __forceinline__ void red2(float* p, float a, float b) {
    asm volatile("red.global.add.v2.f32 [%0], {%1, %2};" :: "l"(p), "f"(a), "f"(b) : "memory");
}
__device__ __forceinline__ uint64_t pack2(float v) {
    uint64_t r; asm("mov.b64 %0, {%1, %1};" : "=l"(r) : "f"(v)); return r;
}
__device__ __forceinline__ uint64_t fma2(uint64_t a, uint64_t b, uint64_t c) {
    uint64_t d; asm("fma.rn.f32x2 %0, %1, %2, %3;" : "=l"(d) : "l"(a), "l"(b), "l"(c)); return d;
}
__device__ __forceinline__ float2 up2(uint64_t v) {
    float2 f; asm("mov.b64 {%0, %1}, %2;" : "=f"(f.x), "=f"(f.y) : "l"(v)); return f;
}

#if TC
__device__ __forceinline__ uint64_t sdesc(uint32_t a) {  // K-major SW128, LBO=1, SBO=64
    return ((uint64_t)2 << 61) | ((uint64_t)1 << 46) | ((uint64_t)64 << 32) |
           ((uint64_t)1 << 16) | ((a >> 4) & 0x3FFF);
}
__device__ __forceinline__ void mma_ss(uint32_t d, uint64_t ad, uint64_t bd, uint32_t en) {
    asm volatile(
        "{\n\t.reg .pred p;\n\tsetp.ne.u32 p, %4, 0;\n\t"
        "tcgen05.mma.cta_group::1.kind::f16 [%0], %1, %2, %3, {%5, %5, %5, %5}, p;\n\t}"
        :: "r"(d), "l"(ad), "l"(bd), "r"(IDESC), "r"(en), "r"(0u) : "memory");
}
__device__ __forceinline__ void mwait(uint32_t mbar, int phase) {
    asm volatile(
        "{\n\t.reg .pred P;\n\tWL%=:\n\t"
        "mbarrier.try_wait.parity.acquire.cta.shared::cta.b64 P, [%0], %1, 0x989680;\n\t"
        "@P bra.uni WD%=;\n\tbra.uni WL%=;\n\tWD%=:\n\t}"
        :: "r"(mbar), "r"((uint32_t)phase) : "memory");
}
#define LDTM32(r, addr) \
    asm volatile("tcgen05.ld.sync.aligned.32x32b.x32.b32 " \
        "{%0,%1,%2,%3,%4,%5,%6,%7,%8,%9,%10,%11,%12,%13,%14,%15," \
        "%16,%17,%18,%19,%20,%21,%22,%23,%24,%25,%26,%27,%28,%29,%30,%31}, [%32];" \
        : "=r"((r)[0]),"=r"((r)[1]),"=r"((r)[2]),"=r"((r)[3]),"=r"((r)[4]),"=r"((r)[5]), \
          "=r"((r)[6]),"=r"((r)[7]),"=r"((r)[8]),"=r"((r)[9]),"=r"((r)[10]),"=r"((r)[11]), \
          "=r"((r)[12]),"=r"((r)[13]),"=r"((r)[14]),"=r"((r)[15]),"=r"((r)[16]),"=r"((r)[17]), \
          "=r"((r)[18]),"=r"((r)[19]),"=r"((r)[20]),"=r"((r)[21]),"=r"((r)[22]),"=r"((r)[23]), \
          "=r"((r)[24]),"=r"((r)[25]),"=r"((r)[26]),"=r"((r)[27]),"=r"((r)[28]),"=r"((r)[29]), \
          "=r"((r)[30]),"=r"((r)[31]) : "r"(addr))

// copy one 128row x 64col bf16 tile (16KB) global -> smem with SW128 swizzle
__device__ __forceinline__ void cptile(char* sm, uint32_t toff,
                                       const __nv_bfloat16* g, int rs, int tid) {
#pragma unroll
    for (int j = 0; j < 4; j++) {
        int i = tid + j * 256;
        int row = i >> 3, c = (i & 7) * 8;
        uint4 v = *(const uint4*)(g + (size_t)row * rs + c);
        uint32_t o = row * 128 + c * 2;
        o ^= (o >> 3) & 0x70;
        *(uint4*)(sm + toff + o) = v;
    }
}
#endif  // TC

// ---- dispatch / prep ----
__global__ void k_zero() { if (threadIdx.x < NE) g_cnt[threadIdx.x] = 0; }

__global__ void k_flag() { if (threadIdx.x == 0) g_use_tc = TC; }

__global__ void k_dispatch(const int* __restrict__ idx, const float* __restrict__ w) {
    int i = blockIdx.x * blockDim.x + threadIdx.x;
    if (i >= NT * TK) return;
    int e = idx[i];
    int p = atomicAdd(&g_cnt[e], 1);
    if (p < CAP) { g_tok[e * CAP + p] = i >> 1; g_wt[e * CAP + p] = w[i]; }
}

__global__ void k_gather(const float* __restrict__ x) {
    if (!g_use_tc) return;
    int e = blockIdx.y, r = blockIdx.x;
    if (r >= min(g_cnt[e], CAP)) return;
    int t = g_tok[e * CAP + r];
    int d = threadIdx.x * 4;
    float4 v = *(const float4*)(x + (size_t)t * DM + d);
    float f0 = __bfloat162float(__float2bfloat16(v.x));
    float f1 = __bfloat162float(__float2bfloat16(v.y));
    float f2 = __bfloat162float(__float2bfloat16(v.z));
    float f3 = __bfloat162float(__float2bfloat16(v.w));
    size_t o = ((size_t)e * CAP + r) * DM + d;
    *(uint2*)(g_ah + o) = make_uint2(pk(f1, f0), pk(f3, f2));
    *(uint2*)(g_al + o) = make_uint2(pk(v.y - f1, v.x - f0), pk(v.w - f3, v.z - f2));
}

// transpose + split: src [E][K][N] f32 -> [E][N][K] bf16 hi/lo
__global__ __launch_bounds__(256) void k_transw(const float* __restrict__ src,
                                                int which, int K, int N) {
    if (!g_use_tc) return;
    __shared__ float ts[32][33];
    __nv_bfloat16 *dh, *dl;
    if (which == 0)      { dh = g_w1h; dl = g_w1l; }
    else if (which == 1) { dh = g_w2h; dl = g_w2l; }
    else                 { dh = g_w3h; dl = g_w3l; }
    int e = blockIdx.z, n0 = blockIdx.x * 32, k0 = blockIdx.y * 32;
    int tx = threadIdx.x & 31, ty = threadIdx.x >> 5;
    const float* s = src + (size_t)e * K * N;
#pragma unroll
    for (int j = 0; j < 4; j++) ts[ty + 8 * j][tx] = s[(size_t)(k0 + ty + 8 * j) * N + n0 + tx];
    __syncthreads();
    __nv_bfloat16* ph = dh + (size_t)e * N * K;
    __nv_bfloat16* pl = dl + (size_t)e * N * K;
#pragma unroll
    for (int j = 0; j < 4; j++) {
        float v = ts[tx][ty + 8 * j];
        size_t o = (size_t)(n0 + ty + 8 * j) * K + k0 + tx;
        __nv_bfloat16 h = __float2bfloat16(v);
        ph[o] = h;
        pl[o] = __float2bfloat16(v - __bfloat162float(h));
    }
}

// ==================== tcgen05 path ====================
__global__ __launch_bounds__(256) void k_gemm1_tc() {
#if TC
    extern __shared__ char sm[];
    const int e = blockIdx.z, m0 = blockIdx.y * 128, n0 = blockIdx.x * 128;
    int cnt = min(g_cnt[e], CAP);
    if (m0 >= cnt) return;
    const int tid = threadIdx.x;
    uint32_t sb = smem_u32(sm);
    if ((tid >> 5) == 0)
        asm volatile("tcgen05.alloc.cta_group::1.sync.aligned.shared::cta.b32 [%0], %1;"
                     :: "r"(sb + 16), "r"(256) : "memory");
    if (tid == 0) {
        asm volatile("mbarrier.init.shared.b64 [%0], 1;" :: "r"(sb + 0) : "memory");
        asm volatile("mbarrier.init.shared.b64 [%0], 1;" :: "r"(sb + 8) : "memory");
    }
    __syncthreads();
    uint32_t tm;
    asm("ld.shared.b32 %0, [%1];" : "=r"(tm) : "r"(sb + 16));

    const __nv_bfloat16* Ah  = g_ah  + ((size_t)e * CAP + m0) * DM;
    const __nv_bfloat16* Al  = g_al  + ((size_t)e * CAP + m0) * DM;
    const __nv_bfloat16* B1h = g_w1h + ((size_t)e * DF + n0) * DM;
    const __nv_bfloat16* B1l = g_w1l + ((size_t)e * DF + n0) * DM;
    const __nv_bfloat16* B2h = g_w2h + ((size_t)e * DF + n0) * DM;
    const __nv_bfloat16* B2l = g_w2l + ((size_t)e * DF + n0) * DM;

    cptile(sm, 1024,          Ah,  DM, tid);
    cptile(sm, 1024 + TS,     Al,  DM, tid);
    cptile(sm, 1024 + 2 * TS, B1h, DM, tid);
    cptile(sm, 1024 + 3 * TS, B1l, DM, tid);
    cptile(sm, 1024 + 4 * TS, B2h, DM, tid);
    cptile(sm, 1024 + 5 * TS, B2l, DM, tid);
    asm volatile("fence.proxy.async.shared::cta;" ::: "memory");

    int ph0 = 0, ph1 = 0;
    for (int t = 0; t < DM / 64; t++) {
        int b = t & 1;
        uint32_t bb = 1024 + b * 6 * TS;
        __syncthreads();
        if (tid == 0) {
            uint64_t dA0 = sdesc(sb + bb),          dA1 = sdesc(sb + bb + TS);
            uint64_t d10 = sdesc(sb + bb + 2 * TS), d11 = sdesc(sb + bb + 3 * TS);
            uint64_t d20 = sdesc(sb + bb + 4 * TS), d21 = sdesc(sb + bb + 5 * TS);
#pragma unroll
            for (int s = 0; s < 4; s++) {
                uint32_t en = (t | s) ? 1u : 0u;
                mma_ss(tm,       dA0 + s * 2, d10 + s * 2, en);
                mma_ss(tm,       dA0 + s * 2, d11 + s * 2, 1u);
                mma_ss(tm,       dA1 + s * 2, d10 + s * 2, 1u);
                mma_ss(tm + 128, dA0 + s * 2, d20 + s * 2, en);
                mma_ss(tm + 128, dA0 + s * 2, d21 + s * 2, 1u);
                mma_ss(tm + 128, dA1 + s * 2, d20 + s * 2, 1u);
            }
            asm volatile("tcgen05.commit.cta_group::1.mbarrier::arrive::one.shared::cluster.b64 [%0];"
                         :: "r"(sb + b * 8) : "memory");
        }
        if (t + 1 < DM / 64) {
            int k0 = (t + 1) * 64;
            uint32_t nb = 1024 + (b ^ 1) * 6 * TS;
            cptile(sm, nb,          Ah  + k0, DM, tid);
            cptile(sm, nb + TS,     Al  + k0, DM, tid);
            cptile(sm, nb + 2 * TS, B1h + k0, DM, tid);
            cptile(sm, nb + 3 * TS, B1l + k0, DM, tid);
            cptile(sm, nb + 4 * TS, B2h + k0, DM, tid);
            cptile(sm, nb + 5 * TS, B2l + k0, DM, tid);
            asm volatile("fence.proxy.async.shared::cta;" ::: "memory");
        }
        if (b == 0) { mwait(sb + 0, ph0); ph0 ^= 1; }
        else        { mwait(sb + 8, ph1); ph1 ^= 1; }
    }
    asm volatile("tcgen05.fence::after_thread_sync;" ::: "memory");

    if (tid < 128) {
        size_t hr = ((size_t)e * CAP + m0 + tid) * DF + n0;
#pragma unroll 1
        for (int c = 0; c < 4; c++) {
            uint32_t gg[32], vv[32];
            LDTM32(gg, tm + c * 32);
            LDTM32(vv, tm + 128 + c * 32);
            asm volatile("tcgen05.wait::ld.sync.aligned;" ::: "memory");
            uint32_t hb[16], lb[16];
#pragma unroll
            for (int j = 0; j < 16; j++) {
                float g0 = __uint_as_float(gg[2 * j]),     v0 = __uint_as_float(vv[2 * j]);
                float g1 = __uint_as_float(gg[2 * j + 1]), v1 = __uint_as_float(vv[2 * j + 1]);
                float h0 = g0 / (1.0f + __expf(-g0)) * v0;
                float h1 = g1 / (1.0f + __expf(-g1)) * v1;
                float f0 = __bfloat162float(__float2bfloat16(h0));
                float f1 = __bfloat162float(__float2bfloat16(h1));
                hb[j] = pk(f1, f0);
                lb[j] = pk(h1 - f1, h0 - f0);
            }
#pragma unroll
            for (int q = 0; q < 4; q++) {
                *(uint4*)(g_hh + hr + c * 32 + q * 8) =
                    make_uint4(hb[4 * q], hb[4 * q + 1], hb[4 * q + 2], hb[4 * q + 3]);
                *(uint4*)(g_hl + hr + c * 32 + q * 8) =
                    make_uint4(lb[4 * q], lb[4 * q + 1], lb[4 * q + 2], lb[4 * q + 3]);
            }
        }
    }
    __syncthreads();
    if ((tid >> 5) == 0) {
        asm volatile("tcgen05.relinquish_alloc_permit.cta_group::1.sync.aligned;");
        asm volatile("tcgen05.dealloc.cta_group::1.sync.aligned.b32 %0, %1;" :: "r"(tm), "r"(256));
    }
#endif
}

__global__ __launch_bounds__(256) void k_gemm2_tc(float* __restrict__ out) {
#if TC
    extern __shared__ char sm[];
    const int e = blockIdx.z, m0 = blockIdx.y * 128, n0 = blockIdx.x * 128;
    int cnt = min(g_cnt[e], CAP);
    if (m0 >= cnt) return;
    const int tid = threadIdx.x;
    uint32_t sb = smem_u32(sm);
    if ((tid >> 5) == 0)
        asm volatile("tcgen05.alloc.cta_group::1.sync.aligned.shared::cta.b32 [%0], %1;"
                     :: "r"(sb + 16), "r"(256) : "memory");
    if (tid == 0) {
        asm volatile("mbarrier.init.shared.b64 [%0], 1;" :: "r"(sb + 0) : "memory");
        asm volatile("mbarrier.init.shared.b64 [%0], 1;" :: "r"(sb + 8) : "memory");
    }
    __syncthreads();
    uint32_t tm;
    asm("ld.shared.b32 %0, [%1];" : "=r"(tm) : "r"(sb + 16));

    const __nv_bfloat16* Ah = g_hh  + ((size_t)e * CAP + m0) * DF;
    const __nv_bfloat16* Al = g_hl  + ((size_t)e * CAP + m0) * DF;
    const __nv_bfloat16* Bh = g_w3h + ((size_t)e * DM + n0) * DF;
    const __nv_bfloat16* Bl = g_w3l + ((size_t)e * DM + n0) * DF;

    cptile(sm, 1024,          Ah, DF, tid);
    cptile(sm, 1024 + TS,     Al, DF, tid);
    cptile(sm, 1024 + 2 * TS, Bh, DF, tid);
    cptile(sm, 1024 + 3 * TS, Bl, DF, tid);
    asm volatile("fence.proxy.async.shared::cta;" ::: "memory");

    int ph0 = 0, ph1 = 0;
    for (int t = 0; t < DF / 64; t++) {
        int b = t & 1;
        uint32_t bb = 1024 + b * 4 * TS;
        __syncthreads();
        if (tid == 0) {
            uint64_t dA0 = sdesc(sb + bb),          dA1 = sdesc(sb + bb + TS);
            uint64_t dB0 = sdesc(sb + bb + 2 * TS), dB1 = sdesc(sb + bb + 3 * TS);
#pragma unroll
            for (int s = 0; s < 4; s++) {
                uint32_t en = (t | s) ? 1u : 0u;
                mma_ss(tm, dA0 + s * 2, dB0 + s * 2, en);
                mma_ss(tm, dA0 + s * 2, dB1 + s * 2, 1u);
                mma_ss(tm, dA1 + s * 2, dB0 + s * 2, 1u);
            }
            asm volatile("tcgen05.commit.cta_group::1.mbarrier::arrive::one.shared::cluster.b64 [%0];"
                         :: "r"(sb + b * 8) : "memory");
        }
        if (t + 1 < DF / 64) {
            int k0 = (t + 1) * 64;
            uint32_t nb = 1024 + (b ^ 1) * 4 * TS;
            cptile(sm, nb,          Ah + k0, DF, tid);
            cptile(sm, nb + TS,     Al + k0, DF, tid);
            cptile(sm, nb + 2 * TS, Bh + k0, DF, tid);
            cptile(sm, nb + 3 * TS, Bl + k0, DF, tid);
            asm volatile("fence.proxy.async.shared::cta;" ::: "memory");
        }
        if (b == 0) { mwait(sb + 0, ph0); ph0 ^= 1; }
        else        { mwait(sb + 8, ph1); ph1 ^= 1; }
    }
    asm volatile("tcgen05.fence::after_thread_sync;" ::: "memory");

    if (tid < 128) {
        bool val = (m0 + tid) < cnt;
        int tok = 0; float w = 0.0f;
        if (val) { tok = g_tok[e * CAP + m0 + tid]; w = g_wt[e * CAP + m0 + tid]; }
#pragma unroll 1
        for (int c = 0; c < 4; c++) {
            uint32_t dd[32];
            LDTM32(dd, tm + c * 32);
            asm volatile("tcgen05.wait::ld.sync.aligned;" ::: "memory");
            if (val) {
                float* o = out + (size_t)tok * DM + n0 + c * 32;
#pragma unroll
                for (int j = 0; j < 16; j++)
                    red2(o + 2 * j, w * __uint_as_float(dd[2 * j]),
                                    w * __uint_as_float(dd[2 * j + 1]));
            }
        }
    }
    __syncthreads();
    if ((tid >> 5) == 0) {
        asm volatile("tcgen05.relinquish_alloc_permit.cta_group::1.sync.aligned;");
        asm volatile("tcgen05.dealloc.cta_group::1.sync.aligned.b32 %0, %1;" :: "r"(tm), "r"(256));
    }
#endif
}

// ==================== SIMT fallback (proven R2 kernels) ====================
__global__ __launch_bounds__(256, 2) void k_g1s(const float* __restrict__ x,
                                                const float* __restrict__ w1,
                                                const float* __restrict__ w2) {
    if (g_use_tc) return;
    const int e   = blockIdx.z;
    const int cnt = g_cnt[e];
    const int m0  = blockIdx.y * 128;
    if (m0 >= cnt) return;
    const int n0  = blockIdx.x * 64;

    __shared__ float As[2][16][132];
    __shared__ float B1s[2][16][64];
    __shared__ float B2s[2][16][64];
    __shared__ int   toks[128];

    const int tid = threadIdx.x;
    if (tid < 128) toks[tid] = g_tok[e * CAP + m0 + tid];
    __syncthreads();

    const int ar  = tid >> 2;
    const int akq = (tid & 3) * 4;
    const float* ap0 = x + (size_t)toks[ar]      * DM + akq;
    const float* ap1 = x + (size_t)toks[ar + 64] * DM + akq;

    const int bkr = tid >> 4;
    const int bnc = (tid & 15) * 4;
    const float* b1p = w1 + (size_t)e * DM * DF + (size_t)bkr * DF + n0 + bnc;
    const float* b2p = w2 + (size_t)e * DM * DF + (size_t)bkr * DF + n0 + bnc;

    const int tx = tid & 15, ty = tid >> 4;

    uint64_t acc1[8][2], acc2[8][2];
#pragma unroll
    for (int i = 0; i < 8; i++) { acc1[i][0] = acc1[i][1] = 0ull; acc2[i][0] = acc2[i][1] = 0ull; }

    float4 ra0 = *(const float4*)(ap0);
    float4 ra1 = *(const float4*)(ap1);
    float4 rb1 = *(const float4*)(b1p);
    float4 rb2 = *(const float4*)(b2p);

    int buf = 0;
    for (int t = 0; t < DM / 16; t++) {
        As[buf][akq + 0][ar] = ra0.x; As[buf][akq + 1][ar] = ra0.y;
        As[buf][akq + 2][ar] = ra0.z; As[buf][akq + 3][ar] = ra0.w;
        As[buf][akq + 0][ar + 64] = ra1.x; As[buf][akq + 1][ar + 64] = ra1.y;
        As[buf][akq + 2][ar + 64] = ra1.z; As[buf][akq + 3][ar + 64] = ra1.w;
        *(float4*)&B1s[buf][bkr][bnc] = rb1;
        *(float4*)&B2s[buf][bkr][bnc] = rb2;
        __syncthreads();

        if (t + 1 < DM / 16) {
            int k0 = (t + 1) * 16;
            ra0 = *(const float4*)(ap0 + k0);
            ra1 = *(const float4*)(ap1 + k0);
            rb1 = *(const float4*)(b1p + (size_t)k0 * DF);
            rb2 = *(const float4*)(b2p + (size_t)k0 * DF);
        }

#pragma unroll
        for (int kk = 0; kk < 16; kk++) {
            float4 a0 = *(const float4*)&As[buf][kk][ty * 8];
            float4 a1 = *(const float4*)&As[buf][kk][ty * 8 + 4];
            uint64_t aa[8] = {pack2(a0.x), pack2(a0.y), pack2(a0.z), pack2(a0.w),
                              pack2(a1.x), pack2(a1.y), pack2(a1.z), pack2(a1.w)};
            const uint64_t* b1 = (const uint64_t*)&B1s[buf][kk][tx * 4];
            const uint64_t* b2 = (const uint64_t*)&B2s[buf][kk][tx * 4];
            uint64_t b10 = b1[0], b11 = b1[1], b20 = b2[0], b21 = b2[1];
#pragma unroll
            for (int i = 0; i < 8; i++) {
                acc1[i][0] = fma2(aa[i], b10, acc1[i][0]);
                acc1[i][1] = fma2(aa[i], b11, acc1[i][1]);
                acc2[i][0] = fma2(aa[i], b20, acc2[i][0]);
                acc2[i][1] = fma2(aa[i], b21, acc2[i][1]);
            }
        }
        buf ^= 1;
    }

#pragma unroll
    for (int i = 0; i < 8; i++) {
        float* hrow = g_hidden + (size_t)(e * CAP + m0 + ty * 8 + i) * DF + n0 + tx * 4;
        float2 g0 = up2(acc1[i][0]), g1 = up2(acc1[i][1]);
        float2 v0 = up2(acc2[i][0]), v1 = up2(acc2[i][1]);
        float4 h;
        h.x = g0.x / (1.0f + __expf(-g0.x)) * v0.x;
        h.y = g0.y / (1.0f + __expf(-g0.y)) * v0.y;
        h.z = g1.x / (1.0f + __expf(-g1.x)) * v1.x;
        h.w = g1.y / (1.0f + __expf(-g1.y)) * v1.y;
        *(float4*)hrow = h;
    }
}

__global__ __launch_bounds__(256, 2) void k_g2s(const float* __restrict__ w3,
                                                float* __restrict__ out) {
    if (g_use_tc) return;
    const int e   = blockIdx.z;
    const int cnt = g_cnt[e];
    const int m0  = blockIdx.y * 128;
    if (m0 >= cnt) return;
    const int n0  = blockIdx.x * 128;

    __shared__ float As[2][16][132];
    __shared__ float Bs[2][16][128];
    __shared__ int   toks[128];
    __shared__ float wts[128];

    const int tid = threadIdx.x;
    if (tid < 128) { toks[tid] = g_tok[e * CAP + m0 + tid]; wts[tid] = g_wt[e * CAP + m0 + tid]; }

    const int ar  = tid >> 2;
    const int akq = (tid & 3) * 4;
    const float* ap0 = g_hidden + (size_t)(e * CAP + m0 + ar) * DF + akq;
    const float* ap1 = ap0 + (size_t)64 * DF;

    const int bkr = tid >> 5;
    const int bnc = (tid & 31) * 4;
    const float* bp = w3 + (size_t)e * DF * DM + (size_t)bkr * DM + n0 + bnc;

    const int tx = tid & 15, ty = tid >> 4;

    uint64_t acc[8][4];
#pragma unroll
    for (int i = 0; i < 8; i++) { acc[i][0] = acc[i][1] = acc[i][2] = acc[i][3] = 0ull; }

    float4 ra0 = *(const float4*)(ap0);
    float4 ra1 = *(const float4*)(ap1);
    float4 rb0 = *(const float4*)(bp);
    float4 rb1 = *(const float4*)(bp + (size_t)8 * DM);

    int buf = 0;
    for (int t = 0; t < DF / 16; t++) {
        As[buf][akq + 0][ar] = ra0.x; As[buf][akq + 1][ar] = ra0.y;
        As[buf][akq + 2][ar] = ra0.z; As[buf][akq + 3][ar] = ra0.w;
        As[buf][akq + 0][ar + 64] = ra1.x; As[buf][akq + 1][ar + 64] = ra1.y;
        As[buf][akq + 2][ar + 64] = ra1.z; As[buf][akq + 3][ar + 64] = ra1.w;
        *(float4*)&Bs[buf][bkr][bnc]     = rb0;
        *(float4*)&Bs[buf][bkr + 8][bnc] = rb1;
        __syncthreads();

        if (t + 1 < DF / 16) {
            int k0 = (t + 1) * 16;
            ra0 = *(const float4*)(ap0 + k0);
            ra1 = *(const float4*)(ap1 + k0);
            rb0 = *(const float4*)(bp + (size_t)k0 * DM);
            rb1 = *(const float4*)(bp + (size_t)(k0 + 8) * DM);
        }

#pragma unroll
        for (int kk = 0; kk < 16; kk++) {
            float4 a0 = *(const float4*)&As[buf][kk][ty * 8];
            float4 a1 = *(const float4*)&As[buf][kk][ty * 8 + 4];
            uint64_t aa[8] = {pack2(a0.x), pack2(a0.y), pack2(a0.z), pack2(a0.w),
                              pack2(a1.x), pack2(a1.y), pack2(a1.z), pack2(a1.w)};
            const uint64_t* bL = (const uint64_t*)&Bs[buf][kk][tx * 4];
            const uint64_t* bH = (const uint64_t*)&Bs[buf][kk][64 + tx * 4];
            uint64_t b0 = bL[0], b1 = bL[1], b2 = bH[0], b3 = bH[1];
#pragma unroll
            for (int i = 0; i < 8; i++) {
                acc[i][0] = fma2(aa[i], b0, acc[i][0]);
                acc[i][1] = fma2(aa[i], b1, acc[i][1]);
                acc[i][2] = fma2(aa[i], b2, acc[i][2]);
                acc[i][3] = fma2(aa[i], b3, acc[i][3]);
            }
        }
        buf ^= 1;
    }

#pragma unroll
    for (int i = 0; i < 8; i++) {
        int r = ty * 8 + i;
        if (m0 + r < cnt) {
            float wgt  = wts[r];
            float* o   = out + (size_t)toks[r] * DM + n0;
            float2 p;
            p = up2(acc[i][0]); red2(o + tx * 4,          wgt * p.x, wgt * p.y);
            p = up2(acc[i][1]); red2(o + tx * 4 + 2,      wgt * p.x, wgt * p.y);
            p = up2(acc[i][2]); red2(o + 64 + tx * 4,     wgt * p.x, wgt * p.y);
            p = up2(acc[i][3]); red2(o + 64 + tx * 4 + 2, wgt * p.x, wgt * p.y);
        }
    }
}

// ---- launch ----
extern "C" void kernel_launch(void* const* d_in, const int* in_sizes, int n_in,
                              void* d_out, int out_size) {
    const float* x   = (const float*)d_in[0];
    const int*   idx = (const int*)  d_in[1];
    const float* ew  = (const float*)d_in[2];
    const float* w1  = (const float*)d_in[3];
    const float* w2  = (const float*)d_in[4];
    const float* w3  = (const float*)d_in[5];
    float* out = (float*)d_out;

    const int SM1 = 1024 + 12 * TS;  // 197632
    const int SM2 = 1024 + 8 * TS;   // 132096
    cudaFuncSetAttribute(k_gemm1_tc, cudaFuncAttributeMaxDynamicSharedMemorySize, SM1);
    cudaFuncSetAttribute(k_gemm2_tc, cudaFuncAttributeMaxDynamicSharedMemorySize, SM2);

    cudaMemsetAsync(out, 0, (size_t)out_size * sizeof(float));
    k_zero<<<1, 32>>>();
    k_flag<<<1, 32>>>();
    k_dispatch<<<(NT * TK + 255) / 256, 256>>>(idx, ew);

    // tcgen05 prep (self-skips when tensor path unavailable)
    k_gather<<<dim3(CAP, NE), 256>>>(x);
    k_transw<<<dim3(DF / 32, DM / 32, NE), 256>>>(w1, 0, DM, DF);
    k_transw<<<dim3(DF / 32, DM / 32, NE), 256>>>(w2, 1, DM, DF);
    k_transw<<<dim3(DM / 32, DF / 32, NE), 256>>>(w3, 2, DF, DM);

    // tensor path (no-op bodies on non-'a' cubin)
    k_gemm1_tc<<<dim3(DF / 128, CAP / 128, NE), 256, SM1>>>();
    k_gemm2_tc<<<dim3(DM / 128, CAP / 128, NE), 256, SM2>>>(out);

    // SIMT fallback (self-skips when tensor path ran)
    k_g1s<<<dim3(DF / 64, CAP / 128, NE), 256>>>(x, w1, w2);
    k_g2s<<<dim3(DM / 128, CAP / 128, NE), 256>>>(w3, out);
}

// round 10
// speedup vs baseline: 7.8543x; 2.0307x over previous
#include <cuda_runtime.h>
#include <cuda_bf16.h>
#include <stdint.h>

#define NT 8192
#define TK 2
#define NE 8
#define DM 1024
#define DF 2048
#define CAP 3072
#define TS 16384           // tile bytes: 128 rows x 64 cols bf16, SW128-swizzled
#define IDESC 0x8200490u   // kind::f16: F32 acc, bf16 A/B, M=128, N=128

#if defined(__CUDA_ARCH__) && (__CUDA_ARCH__ >= 1000) && \
    (defined(__CUDA_ARCH_FEAT_SM103_ALL) || defined(__CUDA_ARCH_FEAT_SM100_ALL) || \
     defined(__CUDA_ARCH_FEAT_SM101_ALL) || defined(__CUDA_ARCH_SPECIFIC__) || \
     defined(__CUDA_ARCH_FAMILY_SPECIFIC__))
#define TC 1
#else
#define TC 0
#endif

// ---- persistent scratch (all tiled+swizzled, zero-initialized) ----
__device__ int   g_cnt[NE];
__device__ int   g_tok[NE * CAP];
__device__ float g_wt[NE * CAP];
// A tiles:  ((e*24+mblk)*16+kblk)   W1/W2: ((e*16+nblk)*16+kblk)
// W3 tiles: ((e*8+nblk)*32+kblk)    H:     ((e*24+mblk)*32+fblk)
__device__ __align__(128) __nv_bfloat16 g_ah[(size_t)NE*CAP*DM], g_al[(size_t)NE*CAP*DM];
__device__ __align__(128) __nv_bfloat16 g_w1h[(size_t)NE*DF*DM], g_w1l[(size_t)NE*DF*DM];
__device__ __align__(128) __nv_bfloat16 g_w2h[(size_t)NE*DF*DM], g_w2l[(size_t)NE*DF*DM];
__device__ __align__(128) __nv_bfloat16 g_w3h[(size_t)NE*DM*DF], g_w3l[(size_t)NE*DM*DF];
__device__ __align__(128) __nv_bfloat16 g_hh[(size_t)NE*CAP*DF], g_hl[(size_t)NE*CAP*DF];

// ---- helpers ----
__device__ __forceinline__ uint32_t smem_u32(const void* p) {
    uint32_t a;
    asm("{ .reg .u64 t; cvta.to.shared.u64 t, %1; cvt.u32.u64 %0, t; }" : "=r"(a) : "l"(p));
    return a;
}
__device__ __forceinline__ uint32_t pk(float hi, float lo) {
    uint32_t r; asm("cvt.rn.bf16x2.f32 %0, %1, %2;" : "=r"(r) : "f"(hi), "f"(lo)); return r;
}
__device__ __forceinline__ void red2(float* p, float a, float b) {
    asm volatile("red.global.add.v2.f32 [%0], {%1, %2};" :: "l"(p), "f"(a), "f"(b) : "memory");
}
__device__ __forceinline__ uint32_t swz(uint32_t o) { return o ^ ((o >> 3) & 0x70); }

#if TC
__device__ __forceinline__ uint64_t sdesc(uint32_t a) {  // K-major SW128, LBO=1, SBO=64
    return ((uint64_t)2 << 61) | ((uint64_t)1 << 46) | ((uint64_t)64 << 32) |
           ((uint64_t)1 << 16) | ((a >> 4) & 0x3FFF);
}
__device__ __forceinline__ void mma_ss(uint32_t d, uint64_t ad, uint64_t bd, uint32_t en) {
    asm volatile(
        "{\n\t.reg .pred p;\n\tsetp.ne.u32 p, %4, 0;\n\t"
        "tcgen05.mma.cta_group::1.kind::f16 [%0], %1, %2, %3, {%5, %5, %5, %5}, p;\n\t}"
        :: "r"(d), "l"(ad), "l"(bd), "r"(IDESC), "r"(en), "r"(0u) : "memory");
}
__device__ __forceinline__ void mwait(uint32_t mbar, int phase) {
    asm volatile(
        "{\n\t.reg .pred P;\n\tWL%=:\n\t"
        "mbarrier.try_wait.parity.acquire.cta.shared::cta.b64 P, [%0], %1, 0x989680;\n\t"
        "@P bra.uni WD%=;\n\tbra.uni WL%=;\n\tWD%=:\n\t}"
        :: "r"(mbar), "r"((uint32_t)phase) : "memory");
}
__device__ __forceinline__ void bulkcp(uint32_t dst, const void* src, uint32_t mbar) {
    asm volatile(
        "cp.async.bulk.shared::cluster.global.mbarrier::complete_tx::bytes [%0], [%1], %2, [%3];"
        :: "r"(dst), "l"(src), "r"((uint32_t)TS), "r"(mbar) : "memory");
}
__device__ __forceinline__ void expect_tx(uint32_t mbar, uint32_t bytes) {
    asm volatile("mbarrier.arrive.expect_tx.shared.b64 _, [%0], %1;"
                 :: "r"(mbar), "r"(bytes) : "memory");
}
__device__ __forceinline__ void mbinit(uint32_t mbar) {
    asm volatile("mbarrier.init.shared.b64 [%0], 1;" :: "r"(mbar) : "memory");
}
__device__ __forceinline__ void commit_to(uint32_t mbar) {
    asm volatile("tcgen05.commit.cta_group::1.mbarrier::arrive::one.shared::cluster.b64 [%0];"
                 :: "r"(mbar) : "memory");
}
#define LDTM32(r, addr) \
    asm volatile("tcgen05.ld.sync.aligned.32x32b.x32.b32 " \
        "{%0,%1,%2,%3,%4,%5,%6,%7,%8,%9,%10,%11,%12,%13,%14,%15," \
        "%16,%17,%18,%19,%20,%21,%22,%23,%24,%25,%26,%27,%28,%29,%30,%31}, [%32];" \
        : "=r"((r)[0]),"=r"((r)[1]),"=r"((r)[2]),"=r"((r)[3]),"=r"((r)[4]),"=r"((r)[5]), \
          "=r"((r)[6]),"=r"((r)[7]),"=r"((r)[8]),"=r"((r)[9]),"=r"((r)[10]),"=r"((r)[11]), \
          "=r"((r)[12]),"=r"((r)[13]),"=r"((r)[14]),"=r"((r)[15]),"=r"((r)[16]),"=r"((r)[17]), \
          "=r"((r)[18]),"=r"((r)[19]),"=r"((r)[20]),"=r"((r)[21]),"=r"((r)[22]),"=r"((r)[23]), \
          "=r"((r)[24]),"=r"((r)[25]),"=r"((r)[26]),"=r"((r)[27]),"=r"((r)[28]),"=r"((r)[29]), \
          "=r"((r)[30]),"=r"((r)[31]) : "r"(addr))
#endif  // TC

// ---- dispatch / prep ----
__global__ void k_zero() { if (threadIdx.x < NE) g_cnt[threadIdx.x] = 0; }

__global__ void k_dispatch(const int* __restrict__ idx, const float* __restrict__ w) {
    int i = blockIdx.x * blockDim.x + threadIdx.x;
    if (i >= NT * TK) return;
    int e = idx[i];
    int p = atomicAdd(&g_cnt[e], 1);
    if (p < CAP) { g_tok[e * CAP + p] = i >> 1; g_wt[e * CAP + p] = w[i]; }
}

// gather + split into swizzled A tiles
__global__ void k_gather(const float* __restrict__ x) {
    int e = blockIdx.y, r = blockIdx.x;
    if (r >= min(g_cnt[e], CAP)) return;
    int t = g_tok[e * CAP + r];
    int d = threadIdx.x * 4;
    float4 v = *(const float4*)(x + (size_t)t * DM + d);
    float f0 = __bfloat162float(__float2bfloat16(v.x));
    float f1 = __bfloat162float(__float2bfloat16(v.y));
    float f2 = __bfloat162float(__float2bfloat16(v.z));
    float f3 = __bfloat162float(__float2bfloat16(v.w));
    size_t tile = ((size_t)((e * 24 + (r >> 7)) * 16 + (d >> 6))) * TS;
    uint32_t off = swz((uint32_t)(r & 127) * 128 + (d & 63) * 2);
    *(uint2*)((char*)g_ah + tile + off) = make_uint2(pk(f1, f0), pk(f3, f2));
    *(uint2*)((char*)g_al + tile + off) = make_uint2(pk(v.y - f1, v.x - f0), pk(v.w - f3, v.z - f2));
}

// transpose + split: src [E][K][N] f32 -> swizzled tiles [E][nblk][kblk]
__global__ __launch_bounds__(256) void k_transw(const float* __restrict__ src,
                                                int which, int K, int N) {
    __shared__ float ts[32][33];
    __nv_bfloat16 *dh, *dl;
    if (which == 0)      { dh = g_w1h; dl = g_w1l; }
    else if (which == 1) { dh = g_w2h; dl = g_w2l; }
    else                 { dh = g_w3h; dl = g_w3l; }
    const int KB = K / 64;
    int e = blockIdx.z, n0 = blockIdx.x * 32, k0 = blockIdx.y * 32;
    int tx = threadIdx.x & 31, ty = threadIdx.x >> 5;
    const float* s = src + (size_t)e * K * N;
#pragma unroll
    for (int j = 0; j < 4; j++) ts[ty + 8 * j][tx] = s[(size_t)(k0 + ty + 8 * j) * N + n0 + tx];
    __syncthreads();
    int tilesPerE = (N / 128) * KB;
#pragma unroll
    for (int j = 0; j < 4; j++) {
        int n = n0 + ty + 8 * j, k = k0 + tx;
        float v = ts[tx][ty + 8 * j];
        size_t tile = ((size_t)(e * tilesPerE + (n >> 7) * KB + (k >> 6))) * TS;
        uint32_t off = swz((uint32_t)(n & 127) * 128 + (k & 63) * 2);
        __nv_bfloat16 h = __float2bfloat16(v);
        *(__nv_bfloat16*)((char*)dh + tile + off) = h;
        *(__nv_bfloat16*)((char*)dl + tile + off) = __float2bfloat16(v - __bfloat162float(h));
    }
}

// ==================== GEMM1: gate/value, bulk-async pipeline ====================
// grid (16, 24, 8), M=128 N=128, 16 K-stages of 64, 6 tiles/stage, 2-stage buffer
__global__ __launch_bounds__(256) void k_gemm1_tc() {
#if TC
    extern __shared__ char sm[];
    const int e = blockIdx.z, mblk = blockIdx.y, nblk = blockIdx.x;
    const int m0 = mblk * 128;
    int cnt = min(g_cnt[e], CAP);
    if (m0 >= cnt) return;
    const int tid = threadIdx.x;
    uint32_t sb = smem_u32(sm);
    if ((tid >> 5) == 0)
        asm volatile("tcgen05.alloc.cta_group::1.sync.aligned.shared::cta.b32 [%0], %1;"
                     :: "r"(sb + 32), "r"(256) : "memory");
    if (tid == 0) {
        mbinit(sb + 0); mbinit(sb + 8); mbinit(sb + 16); mbinit(sb + 24);
        asm volatile("fence.proxy.async.shared::cta;" ::: "memory");
    }
    __syncthreads();
    uint32_t tm;
    asm("ld.shared.b32 %0, [%1];" : "=r"(tm) : "r"(sb + 32));

    const char* aH = (const char*)g_ah  + (size_t)((e * 24 + mblk) * 16) * TS;
    const char* aL = (const char*)g_al  + (size_t)((e * 24 + mblk) * 16) * TS;
    const char* w1H = (const char*)g_w1h + (size_t)((e * 16 + nblk) * 16) * TS;
    const char* w1L = (const char*)g_w1l + (size_t)((e * 16 + nblk) * 16) * TS;
    const char* w2H = (const char*)g_w2h + (size_t)((e * 16 + nblk) * 16) * TS;
    const char* w2L = (const char*)g_w2l + (size_t)((e * 16 + nblk) * 16) * TS;

    if (tid == 0) {
#pragma unroll
        for (int b = 0; b < 2; b++) {
            uint32_t st = sb + 1024 + b * 6 * TS, fb = sb + b * 8;
            expect_tx(fb, 6 * TS);
            size_t ko = (size_t)b * TS;
            bulkcp(st,          aH  + ko, fb); bulkcp(st + TS,     aL  + ko, fb);
            bulkcp(st + 2 * TS, w1H + ko, fb); bulkcp(st + 3 * TS, w1L + ko, fb);
            bulkcp(st + 4 * TS, w2H + ko, fb); bulkcp(st + 5 * TS, w2L + ko, fb);
        }
        int pf0 = 0, pf1 = 0, pd0 = 0, pd1 = 0;
        for (int t = 0; t < 16; t++) {
            int b = t & 1;
            uint32_t st = sb + 1024 + b * 6 * TS;
            if (b == 0) { mwait(sb + 0, pf0); pf0 ^= 1; }
            else        { mwait(sb + 8, pf1); pf1 ^= 1; }
            uint64_t dA = sdesc(st),          dAl = sdesc(st + TS);
            uint64_t d1 = sdesc(st + 2 * TS), d1l = sdesc(st + 3 * TS);
            uint64_t d2 = sdesc(st + 4 * TS), d2l = sdesc(st + 5 * TS);
#pragma unroll
            for (int s = 0; s < 4; s++) {
                uint32_t en = (t | s) ? 1u : 0u;
                mma_ss(tm,       dA  + s * 2, d1  + s * 2, en);
                mma_ss(tm,       dA  + s * 2, d1l + s * 2, 1u);
                mma_ss(tm,       dAl + s * 2, d1  + s * 2, 1u);
                mma_ss(tm + 128, dA  + s * 2, d2  + s * 2, en);
                mma_ss(tm + 128, dA  + s * 2, d2l + s * 2, 1u);
                mma_ss(tm + 128, dAl + s * 2, d2  + s * 2, 1u);
            }
            commit_to(sb + 16 + b * 8);
            if (t + 2 < 16) {
                if (b == 0) { mwait(sb + 16, pd0); pd0 ^= 1; }
                else        { mwait(sb + 24, pd1); pd1 ^= 1; }
                uint32_t fb = sb + b * 8;
                expect_tx(fb, 6 * TS);
                size_t ko = (size_t)(t + 2) * TS;
                bulkcp(st,          aH  + ko, fb); bulkcp(st + TS,     aL  + ko, fb);
                bulkcp(st + 2 * TS, w1H + ko, fb); bulkcp(st + 3 * TS, w1L + ko, fb);
                bulkcp(st + 4 * TS, w2H + ko, fb); bulkcp(st + 5 * TS, w2L + ko, fb);
            }
        }
        mwait(sb + 16, pd0);
        mwait(sb + 24, pd1);
    }
    __syncthreads();
    asm volatile("tcgen05.fence::after_thread_sync;" ::: "memory");

    // epilogue: silu(gate)*value -> swizzled hidden tiles (all 8 warps; warps 4-7 take c=2,3)
    {
        int row = tid & 127;
        int cb  = (tid >> 7) * 2;
        size_t hb0 = (size_t)((e * 24 + mblk) * 32 + nblk * 2) * TS;  // fblk base = nblk*2
#pragma unroll 1
        for (int ci = 0; ci < 2; ci++) {
            int c = cb + ci;
            uint32_t gg[32], vv[32];
            LDTM32(gg, tm + c * 32);
            LDTM32(vv, tm + 128 + c * 32);
            asm volatile("tcgen05.wait::ld.sync.aligned;" ::: "memory");
            uint32_t hbuf[16], lbuf[16];
#pragma unroll
            for (int j = 0; j < 16; j++) {
                float g0 = __uint_as_float(gg[2 * j]),     v0 = __uint_as_float(vv[2 * j]);
                float g1 = __uint_as_float(gg[2 * j + 1]), v1 = __uint_as_float(vv[2 * j + 1]);
                float h0 = g0 / (1.0f + __expf(-g0)) * v0;
                float h1 = g1 / (1.0f + __expf(-g1)) * v1;
                float f0 = __bfloat162float(__float2bfloat16(h0));
                float f1 = __bfloat162float(__float2bfloat16(h1));
                hbuf[j] = pk(f1, f0);
                lbuf[j] = pk(h1 - f1, h0 - f0);
            }
            size_t tb = hb0 + (size_t)(c >> 1) * TS;          // fblk = nblk*2 + c/2
            uint32_t cbase = (uint32_t)(c & 1) * 64;          // byte col base within tile row
#pragma unroll
            for (int q = 0; q < 4; q++) {
                uint32_t off = swz((uint32_t)row * 128 + cbase + q * 16);
                *(uint4*)((char*)g_hh + tb + off) =
                    make_uint4(hbuf[4 * q], hbuf[4 * q + 1], hbuf[4 * q + 2], hbuf[4 * q + 3]);
                *(uint4*)((char*)g_hl + tb + off) =
                    make_uint4(lbuf[4 * q], lbuf[4 * q + 1], lbuf[4 * q + 2], lbuf[4 * q + 3]);
            }
        }
    }
    __syncthreads();
    if ((tid >> 5) == 0) {
        asm volatile("tcgen05.relinquish_alloc_permit.cta_group::1.sync.aligned;");
        asm volatile("tcgen05.dealloc.cta_group::1.sync.aligned.b32 %0, %1;" :: "r"(tm), "r"(256));
    }
#endif
}

// ==================== GEMM2: hidden @ w3^T, M=256, weighted scatter ====================
// grid (8, 12, 8), 32 K-stages of 64, 6 tiles/stage (a0h,a0l,a1h,a1l,bh,bl)
__global__ __launch_bounds__(256) void k_gemm2_tc(float* __restrict__ out) {
#if TC
    extern __shared__ char sm[];
    const int e = blockIdx.z, nblk = blockIdx.x;
    const int m0 = blockIdx.y * 256, n0 = nblk * 128;
    int cnt = min(g_cnt[e], CAP);
    if (m0 >= cnt) return;
    const int tid = threadIdx.x;
    uint32_t sb = smem_u32(sm);
    if ((tid >> 5) == 0)
        asm volatile("tcgen05.alloc.cta_group::1.sync.aligned.shared::cta.b32 [%0], %1;"
                     :: "r"(sb + 32), "r"(256) : "memory");
    if (tid == 0) {
        mbinit(sb + 0); mbinit(sb + 8); mbinit(sb + 16); mbinit(sb + 24);
        asm volatile("fence.proxy.async.shared::cta;" ::: "memory");
    }
    __syncthreads();
    uint32_t tm;
    asm("ld.shared.b32 %0, [%1];" : "=r"(tm) : "r"(sb + 32));

    const int mb = blockIdx.y * 2;
    const char* a0H = (const char*)g_hh  + (size_t)((e * 24 + mb)     * 32) * TS;
    const char* a0L = (const char*)g_hl  + (size_t)((e * 24 + mb)     * 32) * TS;
    const char* a1H = (const char*)g_hh  + (size_t)((e * 24 + mb + 1) * 32) * TS;
    const char* a1L = (const char*)g_hl  + (size_t)((e * 24 + mb + 1) * 32) * TS;
    const char* bH  = (const char*)g_w3h + (size_t)((e * 8 + nblk)    * 32) * TS;
    const char* bL  = (const char*)g_w3l + (size_t)((e * 8 + nblk)    * 32) * TS;

    if (tid == 0) {
#pragma unroll
        for (int b = 0; b < 2; b++) {
            uint32_t st = sb + 1024 + b * 6 * TS, fb = sb + b * 8;
            expect_tx(fb, 6 * TS);
            size_t ko = (size_t)b * TS;
            bulkcp(st,          a0H + ko, fb); bulkcp(st + TS,     a0L + ko, fb);
            bulkcp(st + 2 * TS, a1H + ko, fb); bulkcp(st + 3 * TS, a1L + ko, fb);
            bulkcp(st + 4 * TS, bH  + ko, fb); bulkcp(st + 5 * TS, bL  + ko, fb);
        }
        int pf0 = 0, pf1 = 0, pd0 = 0, pd1 = 0;
        for (int t = 0; t < 32; t++) {
            int b = t & 1;
            uint32_t st = sb + 1024 + b * 6 * TS;
            if (b == 0) { mwait(sb + 0, pf0); pf0 ^= 1; }
            else        { mwait(sb + 8, pf1); pf1 ^= 1; }
            uint64_t dA0 = sdesc(st),          dA0l = sdesc(st + TS);
            uint64_t dA1 = sdesc(st + 2 * TS), dA1l = sdesc(st + 3 * TS);
            uint64_t dB  = sdesc(st + 4 * TS), dBl  = sdesc(st + 5 * TS);
#pragma unroll
            for (int s = 0; s < 4; s++) {
                uint32_t en = (t | s) ? 1u : 0u;
                mma_ss(tm,       dA0  + s * 2, dB  + s * 2, en);
                mma_ss(tm,       dA0  + s * 2, dBl + s * 2, 1u);
                mma_ss(tm,       dA0l + s * 2, dB  + s * 2, 1u);
                mma_ss(tm + 128, dA1  + s * 2, dB  + s * 2, en);
                mma_ss(tm + 128, dA1  + s * 2, dBl + s * 2, 1u);
                mma_ss(tm + 128, dA1l + s * 2, dB  + s * 2, 1u);
            }
            commit_to(sb + 16 + b * 8);
            if (t + 2 < 32) {
                if (b == 0) { mwait(sb + 16, pd0); pd0 ^= 1; }
                else        { mwait(sb + 24, pd1); pd1 ^= 1; }
                uint32_t fb = sb + b * 8;
                expect_tx(fb, 6 * TS);
                size_t ko = (size_t)(t + 2) * TS;
                bulkcp(st,          a0H + ko, fb); bulkcp(st + TS,     a0L + ko, fb);
                bulkcp(st + 2 * TS, a1H + ko, fb); bulkcp(st + 3 * TS, a1L + ko, fb);
                bulkcp(st + 4 * TS, bH  + ko, fb); bulkcp(st + 5 * TS, bL  + ko, fb);
            }
        }
        mwait(sb + 16, pd0);
        mwait(sb + 24, pd1);
    }
    __syncthreads();
    asm volatile("tcgen05.fence::after_thread_sync;" ::: "memory");

    // epilogue: warps 0-3 -> m-tile0 (tm), warps 4-7 -> m-tile1 (tm+128)
    {
        int mt  = tid >> 7;
        int row = m0 + mt * 128 + (tid & 127);
        bool val = row < cnt;
        int tok = 0; float w = 0.0f;
        if (val) { tok = g_tok[e * CAP + row]; w = g_wt[e * CAP + row]; }
#pragma unroll 1
        for (int c = 0; c < 4; c++) {
            uint32_t dd[32];
            LDTM32(dd, tm + mt * 128 + c * 32);
            asm volatile("tcgen05.wait::ld.sync.aligned;" ::: "memory");
            if (val) {
                float* o = out + (size_t)tok * DM + n0 + c * 32;
#pragma unroll
                for (int j = 0; j < 16; j++)
                    red2(o + 2 * j, w * __uint_as_float(dd[2 * j]),
                                    w * __uint_as_float(dd[2 * j + 1]));
            }
        }
    }
    __syncthreads();
    if ((tid >> 5) == 0) {
        asm volatile("tcgen05.relinquish_alloc_permit.cta_group::1.sync.aligned;");
        asm volatile("tcgen05.dealloc.cta_group::1.sync.aligned.b32 %0, %1;" :: "r"(tm), "r"(256));
    }
#endif
}

// ---- launch ----
extern "C" void kernel_launch(void* const* d_in, const int* in_sizes, int n_in,
                              void* d_out, int out_size) {
    const float* x   = (const float*)d_in[0];
    const int*   idx = (const int*)  d_in[1];
    const float* ew  = (const float*)d_in[2];
    const float* w1  = (const float*)d_in[3];
    const float* w2  = (const float*)d_in[4];
    const float* w3  = (const float*)d_in[5];
    float* out = (float*)d_out;

    const int SMB = 1024 + 12 * TS;  // 197632 for both GEMMs
    cudaFuncSetAttribute(k_gemm1_tc, cudaFuncAttributeMaxDynamicSharedMemorySize, SMB);
    cudaFuncSetAttribute(k_gemm2_tc, cudaFuncAttributeMaxDynamicSharedMemorySize, SMB);

    cudaMemsetAsync(out, 0, (size_t)out_size * sizeof(float));
    k_zero<<<1, 32>>>();
    k_dispatch<<<(NT * TK + 255) / 256, 256>>>(idx, ew);
    k_gather<<<dim3(CAP, NE), 256>>>(x);
    k_transw<<<dim3(DF / 32, DM / 32, NE), 256>>>(w1, 0, DM, DF);
    k_transw<<<dim3(DF / 32, DM / 32, NE), 256>>>(w2, 1, DM, DF);
    k_transw<<<dim3(DM / 32, DF / 32, NE), 256>>>(w3, 2, DF, DM);

    k_gemm1_tc<<<dim3(DF / 128, CAP / 128, NE), 256, SMB>>>();
    k_gemm2_tc<<<dim3(DM / 128, CAP / 256, NE), 256, SMB>>>(out);
}